// round 5
// baseline (speedup 1.0000x reference)
#include <cuda_runtime.h>
#include <cstdint>
#include <cstddef>

// ============================================================================
// W8A8B8O8 Linear, sm_103 base ISA (tcgen05 unavailable: ptxas target lacks 'a')
//   out[8192,4096] = sat_rne( (x_i8 @ W_i8) * (a*b) )  — harness I/O is 32-bit
//   (int8 tensors promoted by the harness; values are exact small integers).
// Pass 1: convert x -> g_x8 (int8), convert+transpose w[K,N] -> g_wT[N,K] int8.
// Pass 2: GEMM mma.sync m16n8k32 s8, BM=128 BN=256 BK=64, 4-stage cp.async,
//         ldmatrix.x4 fragments, xor-swizzled SMEM; epilogue quantizes (RNE)
//         and stores float32.
// R5 fix: A-operand ldmatrix lane map restored to PTX-ISA a0..a3 order
//         (R4 had a1/a2 swapped -> rel_err ~1).
// ============================================================================

#define DINLINE __device__ __forceinline__

static constexpr int M_TOTAL = 8192;
static constexpr int K_TOTAL = 4096;
static constexpr int N_TOTAL = 4096;

static constexpr int BM = 128;
static constexpr int BN = 256;
static constexpr int BK = 64;
static constexpr int STAGES = 4;
static constexpr int KCHUNKS = K_TOTAL / BK;      // 64
static constexpr int NUM_M = M_TOTAL / BM;        // 64
static constexpr int NUM_N = N_TOTAL / BN;        // 16
static constexpr int GROUP_M = 8;
static constexpr int NTHREADS = 256;              // 8 warps (2x4), warp tile 64x64

static constexpr uint32_t A_BYTES = BM * BK;                  // 8 KB
static constexpr uint32_t B_BYTES = BN * BK;                  // 16 KB
static constexpr uint32_t STAGE_BYTES = A_BYTES + B_BYTES;    // 24 KB
static constexpr uint32_t SMEM_TOTAL = STAGES * STAGE_BYTES;  // 96 KB

// int8 scratch — static __device__ globals, no allocation.
__device__ uint8_t g_x8[(size_t)M_TOTAL * K_TOTAL];   // 32 MB
__device__ uint8_t g_wT[(size_t)N_TOTAL * K_TOTAL];   // 16 MB

// Packed-tile offset: 2 logical rows per 128B smem row; 16B granule index is
// xor-swizzled with the low 3 bits of the smem row.
DINLINE uint32_t swz_addr(uint32_t row128, uint32_t gran) {
    return row128 * 128u + ((gran ^ (row128 & 7u)) << 4);
}

DINLINE uint32_t smem_u32(const void* p) {
    uint32_t r;
    asm("{ .reg .u64 t; cvta.to.shared.u64 t, %1; cvt.u32.u64 %0, t; }" : "=r"(r) : "l"(p));
    return r;
}

DINLINE void cp_async16(uint32_t saddr, const void* gaddr) {
    asm volatile("cp.async.cg.shared.global [%0], [%1], 16;" :: "r"(saddr), "l"(gaddr) : "memory");
}
DINLINE void cp_commit() { asm volatile("cp.async.commit_group;" ::: "memory"); }
DINLINE void cp_wait2() { asm volatile("cp.async.wait_group 2;" ::: "memory"); }

#define LDSM4(r, addr)                                                         \
    asm volatile("ldmatrix.sync.aligned.m8n8.x4.shared.b16 {%0,%1,%2,%3}, [%4];" \
                 : "=r"((r)[0]), "=r"((r)[1]), "=r"((r)[2]), "=r"((r)[3])      \
                 : "r"(addr))

DINLINE void mma_s8(uint32_t* c, const uint32_t* a, uint32_t b0, uint32_t b1) {
    asm volatile(
        "mma.sync.aligned.m16n8k32.row.col.s32.s8.s8.s32 "
        "{%0,%1,%2,%3}, {%4,%5,%6,%7}, {%8,%9}, {%0,%1,%2,%3};"
        : "+r"(c[0]), "+r"(c[1]), "+r"(c[2]), "+r"(c[3])
        : "r"(a[0]), "r"(a[1]), "r"(a[2]), "r"(a[3]), "r"(b0), "r"(b1));
}

DINLINE int q8(int v, float s) {
    int q = __float2int_rn((float)v * s);   // RNE matches jnp.round
    return q < -128 ? -128 : (q > 127 ? 127 : q);
}

// Auto-detect element storage: small int bit-pattern => int32 storage; else
// interpret the bits as float32 and round-to-nearest-even. (Exact for the
// integral values this problem carries; 0 agrees under both readings.)
DINLINE uint8_t cvt_b(uint32_t bits) {
    int v = (int)bits;
    if (v < -128 || v > 127) v = __float2int_rn(__int_as_float(bits));
    v = v < -128 ? -128 : (v > 127 ? 127 : v);
    return (uint8_t)v;
}

// ============================================================================
// x convert: 32-bit-stored values -> g_x8 int8 (same layout [M,K])
// ============================================================================
__global__ void __launch_bounds__(256) x_convert_kernel(const uint32_t* __restrict__ xin) {
    const size_t base = ((size_t)blockIdx.x * 256 + threadIdx.x) * 16;
    alignas(16) uint8_t o[16];
#pragma unroll
    for (int i = 0; i < 16; i += 4) {
        const uint4 v = *reinterpret_cast<const uint4*>(xin + base + i);
        o[i + 0] = cvt_b(v.x);
        o[i + 1] = cvt_b(v.y);
        o[i + 2] = cvt_b(v.z);
        o[i + 3] = cvt_b(v.w);
    }
    *reinterpret_cast<uint4*>(g_x8 + base) = *reinterpret_cast<const uint4*>(o);
}

// ============================================================================
// Weight convert + transpose: w[K,N] (N-contig, 32-bit stored) -> g_wT[N,K] int8
// ============================================================================
__global__ void __launch_bounds__(256) w_convert_transpose(const uint32_t* __restrict__ w) {
    __shared__ uint8_t t[64][65];
    const int tid = threadIdx.x;
    const int n0 = blockIdx.x * 64;
    const int k0 = blockIdx.y * 64;

    const int r = tid >> 2;             // k-row within tile
    const int cseg = (tid & 3) * 16;    // n-col segment
    const uint32_t* src = w + (size_t)(k0 + r) * N_TOTAL + n0 + cseg;
#pragma unroll
    for (int i = 0; i < 16; i += 4) {
        const uint4 v = *reinterpret_cast<const uint4*>(src + i);
        t[r][cseg + i + 0] = cvt_b(v.x);
        t[r][cseg + i + 1] = cvt_b(v.y);
        t[r][cseg + i + 2] = cvt_b(v.z);
        t[r][cseg + i + 3] = cvt_b(v.w);
    }
    __syncthreads();

    const int n = tid >> 2;             // n-row of output
    const int kseg = (tid & 3) * 16;    // k segment
    alignas(16) uint8_t o[16];
#pragma unroll
    for (int j = 0; j < 16; ++j) o[j] = t[kseg + j][n];
    *reinterpret_cast<uint4*>(g_wT + (size_t)(n0 + n) * K_TOTAL + k0 + kseg) =
        *reinterpret_cast<const uint4*>(o);
}

// ============================================================================
// GEMM kernel
// ============================================================================
__global__ void __launch_bounds__(NTHREADS, 1)
w8a8_gemm_kernel(const float* __restrict__ ascale,
                 const float* __restrict__ bscale,
                 float* __restrict__ out) {
    extern __shared__ __align__(1024) uint8_t smem_raw[];
    const uint32_t smem = smem_u32(smem_raw);
    const int t = threadIdx.x;
    const int lane = t & 31;
    const int warp = t >> 5;
    const int wm = warp >> 2;   // 0..1  (64 rows each)
    const int wn = warp & 3;    // 0..3  (64 cols each)

    // --- M-grouped raster: W tiles stay L2-resident while A streams ---
    const int bid = blockIdx.x;
    const int group_sz = GROUP_M * NUM_N;
    const int gid = bid / group_sz;
    const int within = bid - gid * group_sz;
    const int pid_m = gid * GROUP_M + (within % GROUP_M);
    const int pid_n = within / GROUP_M;
    const int m0 = pid_m * BM;
    const int n0 = pid_n * BN;

    // --- producer addresses: 6 x 16B chunks per thread per stage ---
    uint32_t aS[2]; const uint8_t* aG[2];
#pragma unroll
    for (int i = 0; i < 2; ++i) {
        const int q = t + i * NTHREADS;            // 0..511
        const int m = q >> 2, k16 = q & 3;
        aS[i] = smem + swz_addr(m >> 1, (m & 1) * 4 + k16);
        aG[i] = g_x8 + (size_t)(m0 + m) * K_TOTAL + k16 * 16;
    }
    uint32_t bS[4]; const uint8_t* bG[4];
#pragma unroll
    for (int i = 0; i < 4; ++i) {
        const int q = t + i * NTHREADS;            // 0..1023
        const int n = q >> 2, k16 = q & 3;
        bS[i] = smem + A_BYTES + swz_addr(n >> 1, (n & 1) * 4 + k16);
        bG[i] = g_wT + (size_t)(n0 + n) * K_TOTAL + k16 * 16;
    }

    auto load_stage = [&](int s, int chunk) {
        const uint32_t so = s * STAGE_BYTES;
        const size_t ko = (size_t)chunk * BK;
#pragma unroll
        for (int i = 0; i < 2; ++i) cp_async16(aS[i] + so, aG[i] + ko);
#pragma unroll
        for (int i = 0; i < 4; ++i) cp_async16(bS[i] + so, bG[i] + ko);
    };

    // --- consumer ldmatrix lane base OFFSETS (stage 0, mt=0/nt2=0, kp=0) ---
    // A x4 (PTX ISA a0..a3): m0 = rows 0-7 k[0:16), m1 = rows 8-15 k[0:16),
    //                        m2 = rows 0-7 k[16:32), m3 = rows 8-15 k[16:32)
    uint32_t aOff, bOff;
    {
        const int mlocal = ((lane >> 3) & 1) * 8 + (lane & 7);
        const int k16a = lane >> 4;                       // 0 for m0/m1, 1 for m2/m3
        const int am = wm * 64 + mlocal;
        aOff = swz_addr(am >> 1, (am & 1) * 4 + k16a);
        // B x4: m0 = cols 0-7 k[0:16), m1 = cols 0-7 k[16:32),
        //       m2 = cols 8-15 k[0:16), m3 = cols 8-15 k[16:32)
        const int j = lane >> 3;
        const int nlocal = (j >> 1) * 8 + (lane & 7);
        const int k16b = j & 1;
        const int bn = wn * 64 + nlocal;
        bOff = A_BYTES + swz_addr(bn >> 1, (bn & 1) * 4 + k16b);
    }

    uint32_t acc[4][8][4];
#pragma unroll
    for (int mt = 0; mt < 4; ++mt)
#pragma unroll
        for (int nt = 0; nt < 8; ++nt)
#pragma unroll
            for (int r = 0; r < 4; ++r) acc[mt][nt][r] = 0;

    // --- pipeline ---
#pragma unroll
    for (int s = 0; s < STAGES - 1; ++s) { load_stage(s, s); cp_commit(); }

    for (int c = 0; c < KCHUNKS; ++c) {
        cp_wait2();
        __syncthreads();
        const int pf = c + STAGES - 1;
        if (pf < KCHUNKS) load_stage(pf & (STAGES - 1), pf);
        cp_commit();

        const uint32_t so = (c & (STAGES - 1)) * STAGE_BYTES;
#pragma unroll
        for (int kp = 0; kp < 2; ++kp) {
            const uint32_t kx = (uint32_t)kp << 5;   // toggles granule bit1
            uint32_t av[4][4];
#pragma unroll
            for (int mt = 0; mt < 4; ++mt) {
                const uint32_t ad = smem + ((aOff + so + mt * 1024u) ^ kx);
                LDSM4(av[mt], ad);
            }
            uint32_t bv[4][4];
#pragma unroll
            for (int nt2 = 0; nt2 < 4; ++nt2) {
                const uint32_t bd = smem + ((bOff + so + nt2 * 1024u) ^ kx);
                LDSM4(bv[nt2], bd);
            }
#pragma unroll
            for (int mt = 0; mt < 4; ++mt)
#pragma unroll
                for (int nt = 0; nt < 8; ++nt) {
                    const uint32_t* bp = &bv[nt >> 1][(nt & 1) * 2];
                    mma_s8(acc[mt][nt], av[mt], bp[0], bp[1]);
                }
        }
    }

    // --- epilogue: quantize (RNE + clamp) and store float32 ---
    const float scl = ascale[0] * bscale[0];
#pragma unroll
    for (int mt = 0; mt < 4; ++mt) {
#pragma unroll
        for (int nt = 0; nt < 8; ++nt) {
            const int row = m0 + wm * 64 + mt * 16 + (lane >> 2);
            const int col = n0 + wn * 64 + nt * 8 + 2 * (lane & 3);
            const int* a4 = reinterpret_cast<const int*>(acc[mt][nt]);
            float2 v0, v1;
            v0.x = (float)q8(a4[0], scl);
            v0.y = (float)q8(a4[1], scl);
            v1.x = (float)q8(a4[2], scl);
            v1.y = (float)q8(a4[3], scl);
            *reinterpret_cast<float2*>(out + (size_t)row * N_TOTAL + col) = v0;
            *reinterpret_cast<float2*>(out + (size_t)(row + 8) * N_TOTAL + col) = v1;
        }
    }
}

// ============================================================================
// Launch — identify inputs by element count (robust to metadata ordering):
//   x: 8192*4096 = 33554432   weight: 4096*4096 = 16777216   a, b: 1 each
// ============================================================================
extern "C" void kernel_launch(void* const* d_in, const int* in_sizes, int n_in,
                              void* d_out, int out_size) {
    (void)out_size;
    const uint32_t* x = nullptr;
    const uint32_t* w = nullptr;
    const float* s1 = nullptr;
    const float* s2 = nullptr;
    for (int i = 0; i < n_in; ++i) {
        const long sz = in_sizes[i];
        if (sz == (long)M_TOTAL * K_TOTAL) x = (const uint32_t*)d_in[i];
        else if (sz == (long)K_TOTAL * N_TOTAL) w = (const uint32_t*)d_in[i];
        else if (sz == 1) { if (!s1) s1 = (const float*)d_in[i]; else s2 = (const float*)d_in[i]; }
    }
    if (!x || !w || !s1 || !s2) return;

    cudaFuncSetAttribute(w8a8_gemm_kernel,
                         cudaFuncAttributeMaxDynamicSharedMemorySize, (int)SMEM_TOTAL);

    x_convert_kernel<<<(M_TOTAL * K_TOTAL) / (256 * 16), 256>>>(x);
    w_convert_transpose<<<dim3(N_TOTAL / 64, K_TOTAL / 64), 256>>>(w);
    w8a8_gemm_kernel<<<NUM_M * NUM_N, NTHREADS, SMEM_TOTAL>>>(s1, s2, (float*)d_out);
}